// round 16
// baseline (speedup 1.0000x reference)
#include <cuda_runtime.h>
#include <cuda_bf16.h>
#include <cstdint>

// FwFM forward on GB300 — R16: W hoisted to a prep kernel; barrier-free main.
//   second_order[s] = sum_{i<j} w_ij G_ij,  G = E E^T (bf16 HMMA, fp32 accum).
//   Prep kernel writes upper-tri W in MMA fragment layout to wfrag_g (global,
//   4.6 KB, L1-resident). Main kernel: 1 warp = 1 sample, fully warp-local
//   (no __syncthreads): gather 39 rows (10x LDG.64), drain to bf16 tile,
//   9 upper-tri m16n8k16 MMAs, W via one coalesced LDG.128 per tile.

#define FIELDS 39
#define EDIM 16
#define BATCH 8192
#define THREADS 256
#define SPB 8                      // warps (samples) per block
#define TPITCH 48                  // bf16 tile pitch (bytes)
#define TROWS 48
#define TILE_BYTES (TROWS * TPITCH)
#define NTILES 9                   // upper-triangle m16n8k16 tiles

__device__ __align__(16) float wfrag_g[NTILES * 32 * 4];   // [tile][lane][4]

__device__ __forceinline__ uint32_t smem_u32(const void* p) {
    uint32_t a;
    asm("{ .reg .u64 t; cvta.to.shared.u64 t, %1; cvt.u32.u64 %0, t; }" : "=r"(a) : "l"(p));
    return a;
}

__device__ __forceinline__ float wtri(const float* __restrict__ fw, int a, int b) {
    if (a < b && b < FIELDS)
        return __ldg(fw + 38 * a - (a * (a - 1)) / 2 + (b - a - 1));
    return 0.0f;
}

// ---- prep: W -> fragment layout, once per launch ----
__global__ void fwfm_prep(const float* __restrict__ fw)
{
    const int g = threadIdx.x;                 // 0..287
    if (g < NTILES * 32) {
        const int t  = g >> 5;
        const int l  = g & 31;
        const int mi = (t < 5) ? 0 : ((t < 8) ? 1 : 2);
        const int ni = (t < 5) ? t : ((t < 8) ? (t - 3) : 4);
        const int i  = 16 * mi + (l >> 2);
        const int j  = 8 * ni + 2 * (l & 3);
        float4 w;
        w.x = wtri(fw, i,     j);
        w.y = wtri(fw, i,     j + 1);
        w.z = wtri(fw, i + 8, j);
        w.w = wtri(fw, i + 8, j + 1);
        *reinterpret_cast<float4*>(&wfrag_g[g * 4]) = w;
    }
}

// ---- main kernel: barrier-free, warp-local ----
__global__ __launch_bounds__(THREADS, 7)
void fwfm_kernel(const int* __restrict__ inputs,
                 const float* __restrict__ emb,
                 const float* __restrict__ lw,
                 const float* __restrict__ bias,
                 float* __restrict__ out)
{
    __shared__ __align__(128) unsigned char etile[SPB][TILE_BYTES];

    const int tid  = threadIdx.x;
    const int warp = tid >> 5;
    const int lane = tid & 31;
    const int sample = blockIdx.x * SPB + warp;
    const uint32_t T = smem_u32(&etile[warp][0]);

    // ---- indices straight to registers ----
    const int* ixg = inputs + sample * FIELDS;
    const int i0 = __ldg(ixg + lane);                          // fields 0..31
    const int i1 = (lane < FIELDS - 32) ? __ldg(ixg + 32 + lane) : 0;

    // ---- issue all 39 embedding rows first (queue priority) ----
    const int rsub = lane >> 3;
    const int k    = lane & 7;
    float2 v[10];
#pragma unroll
    for (int it = 0; it < 10; it++) {
        const int r = 4 * it + rsub;                           // 0..39 (39 bogus)
        const int g = (r < 32) ? __shfl_sync(0xffffffffu, i0, r)
                               : __shfl_sync(0xffffffffu, i1, r - 32);
        v[it] = *reinterpret_cast<const float2*>(emb + (size_t)g * EDIM + 2 * k);
    }

    // ---- first order (queued after the embedding rows) ----
    float lin = __ldg(lw + i0);
    if (lane < FIELDS - 32) lin += __ldg(lw + i1);

    // ---- drain gathers into the bf16 tile ----
#pragma unroll
    for (int it = 0; it < 10; it++) {
        const int r = 4 * it + rsub;
        uint32_t h;
        asm("cvt.rn.bf16x2.f32 %0, %1, %2;" : "=r"(h) : "f"(v[it].y), "f"(v[it].x));
        asm volatile("st.shared.b32 [%0], %1;" :: "r"(T + r * TPITCH + 4 * k), "r"(h));
    }
    __syncwarp();

    // Zero pad rows 39..47, bytes 0..31 (overwrites the bogus row-39 store).
    if (lane < 18) {
        const uint32_t a = T + (39 + (lane >> 1)) * TPITCH + (lane & 1) * 16;
        asm volatile("st.shared.v4.b32 [%0], {%1,%1,%1,%1};" :: "r"(a), "r"(0));
    }
    __syncwarp();

    // ---- B fragments: 5 n-tiles of 8 rows (B = E, row.col form) ----
    uint32_t b0[5], b1[5];
    {
        const uint32_t bb = T + (lane & 7) * TPITCH + ((lane >> 3) & 1) * 16;
#pragma unroll
        for (int ni = 0; ni < 5; ni++) {
            asm volatile("ldmatrix.sync.aligned.m8n8.x2.shared.b16 {%0,%1}, [%2];"
                         : "=r"(b0[ni]), "=r"(b1[ni]) : "r"(bb + ni * 8 * TPITCH));
        }
    }

    // ---- 9 upper-triangle MMA tiles; W via coalesced LDG.128 (L1-hot) ----
    float acc = 0.0f;
    int t = 0;
#pragma unroll
    for (int mi = 0; mi < 3; mi++) {
        uint32_t a0, a1, a2, a3;
        const uint32_t aa = T + (16 * mi + (lane & 15)) * TPITCH + (lane >> 4) * 16;
        asm volatile("ldmatrix.sync.aligned.m8n8.x4.shared.b16 {%0,%1,%2,%3}, [%4];"
                     : "=r"(a0), "=r"(a1), "=r"(a2), "=r"(a3) : "r"(aa));
#pragma unroll
        for (int ni = 2 * mi; ni < 5; ni++) {
            const float4 w = __ldg(reinterpret_cast<const float4*>(
                                   &wfrag_g[(t * 32 + lane) * 4]));
            float d0, d1, d2, d3;
            asm volatile(
                "mma.sync.aligned.m16n8k16.row.col.f32.bf16.bf16.f32 "
                "{%0,%1,%2,%3}, {%4,%5,%6,%7}, {%8,%9}, {%10,%11,%12,%13};"
                : "=f"(d0), "=f"(d1), "=f"(d2), "=f"(d3)
                : "r"(a0), "r"(a1), "r"(a2), "r"(a3),
                  "r"(b0[ni]), "r"(b1[ni]),
                  "f"(0.0f), "f"(0.0f), "f"(0.0f), "f"(0.0f));
            acc = fmaf(w.x, d0, acc);
            acc = fmaf(w.y, d1, acc);
            acc = fmaf(w.z, d2, acc);
            acc = fmaf(w.w, d3, acc);
            t++;
        }
    }

    float r = acc + lin;
#pragma unroll
    for (int o = 16; o; o >>= 1)
        r += __shfl_xor_sync(0xffffffffu, r, o);

    if (lane == 0)
        out[sample] = r + bias[0];
}

extern "C" void kernel_launch(void* const* d_in, const int* in_sizes, int n_in,
                              void* d_out, int out_size)
{
    const int*   inputs = (const int*)d_in[0];
    const float* emb    = (const float*)d_in[1];
    const float* fw     = (const float*)d_in[2];
    const float* lw     = (const float*)d_in[3];
    const float* bias   = (const float*)d_in[4];
    float*       out    = (float*)d_out;

    fwfm_prep<<<1, 288>>>(fw);
    fwfm_kernel<<<BATCH / SPB, THREADS>>>(inputs, emb, lw, bias, out);
}